// round 9
// baseline (speedup 1.0000x reference)
#include <cuda_runtime.h>
#include <math.h>
#include <string.h>

#define BB 256
#define NN 1024
#define SS 11
#define DD 64
#define HHID 128
#define NITERS 3
#define MESHI 4
#define SHI 5
#define HT 512   /* sinkhorn threads; 2 rows each */

/* ---------------- scratch (device globals: no runtime allocation) ------- */
__device__ float g_k[BB*NN*DD];
__device__ float g_xn[BB*NN*DD];
__device__ float g_ksq[BB*NN];
__device__ float g_wilogit[BB*NN];
__device__ float g_slots[BB*SS*DD];
__device__ float g_q[BB*SS*DD];
__device__ float g_qsq[BB*SS];
__device__ float g_logb[BB*SS];

/* ---------------- helpers ---------------- */
__device__ __forceinline__ float warpSum(float v){
#pragma unroll
  for (int o=16;o>0;o>>=1) v += __shfl_down_sync(0xffffffffu, v, o);
  return v;
}
__device__ __forceinline__ float warpMax(float v){
#pragma unroll
  for (int o=16;o>0;o>>=1) v = fmaxf(v, __shfl_down_sync(0xffffffffu, v, o));
  return v;
}
__device__ __forceinline__ void warpSum4(float&a,float&b,float&c,float&d){
#pragma unroll
  for (int o=16;o>0;o>>=1){
    a += __shfl_down_sync(0xffffffffu, a, o);
    b += __shfl_down_sync(0xffffffffu, b, o);
    c += __shfl_down_sync(0xffffffffu, c, o);
    d += __shfl_down_sync(0xffffffffu, d, o);
  }
}
/* Blackwell packed fp32 FMA: 2 MACs per instruction */
__device__ __forceinline__ float2 ffma2(float2 a, float2 b, float2 c){
  float2 r;
  asm("fma.rn.f32x2 %0, %1, %2, %3;"
      : "=l"(reinterpret_cast<unsigned long long&>(r))
      : "l"(reinterpret_cast<unsigned long long&>(a)),
        "l"(reinterpret_cast<unsigned long long&>(b)),
        "l"(reinterpret_cast<unsigned long long&>(c)));
  return r;
}

/* ------------- kernel: slots = mu + exp(log_sigma)*init ----------------- */
__global__ void slots_init_kernel(const float* __restrict__ sinit,
  const float* __restrict__ mu, const float* __restrict__ lsig)
{
  int idx = blockIdx.x*256 + threadIdx.x;
  if (idx < BB*SS*DD){
    int d = idx & 63;
    g_slots[idx] = mu[d] + expf(lsig[d]) * sinit[idx];
  }
}

/* ------------- slotsnorm: sn=LN(slots), q, qsq, log_b ------------------- */
__global__ void slotsnorm_kernel(const float* __restrict__ Wq,
   const float* __restrict__ lng, const float* __restrict__ lnb,
   const float* __restrict__ ws_w, const float* __restrict__ ws_b)
{
  int b = blockIdx.x;
  int sI = threadIdx.y;  /* 0..10 */
  int d  = threadIdx.x;  /* 0..63 */
  int lane = d&31, half = d>>5;
  __shared__ float sn[11][64];
  __shared__ float part[11][2];
  __shared__ float lg[11];
  int row = b*SS + sI;

  float x = g_slots[row*DD + d];
  float s = warpSum(x);
  if (lane==0) part[sI][half]=s;
  __syncthreads();
  float mean = (part[sI][0]+part[sI][1])*(1.f/64.f);
  float c = x-mean;
  __syncthreads();
  s = warpSum(c*c);
  if (lane==0) part[sI][half]=s;
  __syncthreads();
  float var=(part[sI][0]+part[sI][1])*(1.f/64.f);
  float v = c*rsqrtf(var+1e-5f)*lng[d]+lnb[d];
  sn[sI][d]=v;
  __syncthreads();

  s = warpSum(v*ws_w[d]);
  if (lane==0) part[sI][half]=s;
  __syncthreads();
  if (d==0) lg[sI] = part[sI][0]+part[sI][1] + ws_b[0];

  float qa=0.f;
#pragma unroll 16
  for (int e=0;e<64;e++) qa = fmaf(sn[sI][e], Wq[e*64+d], qa);
  g_q[row*DD+d]=qa;
  __syncthreads();
  s = warpSum(qa*qa);
  if (lane==0) part[sI][half]=s;
  __syncthreads();
  if (d==0) g_qsq[row]=part[sI][0]+part[sI][1];

  if (sI==0 && d==0){
    float M=lg[0];
#pragma unroll
    for (int j=1;j<11;j++) M=fmaxf(M,lg[j]);
    float ss=0.f;
#pragma unroll
    for (int j=0;j<11;j++) ss+=expf(lg[j]-M);
    float lse=M+logf(ss);
#pragma unroll
    for (int j=0;j<11;j++) g_logb[b*SS+j]=lg[j]-lse+2.3978952727983707f;
  }
}

/* ------------- preprocess: LN(inputs) -> xn, k=xn@Wk, ksq, wi logits ---- */
/* 64 rows per block, 256 threads (64 d x 4 ty, 16 rows per ty).            */
/* k GEMM via smem-transposed weights + FFMA2 row pairs.                    */
__global__ void __launch_bounds__(256) preprocess_kernel(
    const float* __restrict__ inp, const float* __restrict__ Wk,
    const float* __restrict__ lng, const float* __restrict__ lnb,
    const float* __restrict__ wi_w, const float* __restrict__ wi_b)
{
  int tid = threadIdx.x;
  int d   = tid & 63;
  int ty  = tid >> 6;
  int lane = tid & 31;
  int half = (d >> 5);
  int row0 = blockIdx.x*64 + ty*16;
  int rl0  = ty*16;                 /* row-local base */

  __shared__ float xsT[64][68];     /* transposed xn: [e][row] */
  __shared__ float WkT[64][68];     /* transposed Wk: [d][e]   */
  __shared__ float part[64][2];

  /* stage WkT */
#pragma unroll
  for (int kk2=0; kk2<16; kk2++){
    int idx = tid + kk2*256;
    int e = idx >> 6, dd = idx & 63;
    WkT[dd][e] = Wk[idx];
  }

  /* ---- LN over 16 rows ---- */
  float x[16];
#pragma unroll
  for (int j=0;j<16;j++) x[j] = inp[(size_t)(row0+j)*DD + d];

#pragma unroll
  for (int g=0; g<4; g++){
    float s0=x[g*4+0], s1=x[g*4+1], s2=x[g*4+2], s3=x[g*4+3];
    warpSum4(s0,s1,s2,s3);
    if (lane==0){ part[rl0+g*4+0][half]=s0; part[rl0+g*4+1][half]=s1;
                  part[rl0+g*4+2][half]=s2; part[rl0+g*4+3][half]=s3; }
  }
  __syncthreads();
#pragma unroll
  for (int j=0;j<16;j++) x[j] -= (part[rl0+j][0]+part[rl0+j][1])*(1.f/64.f);
  __syncthreads();
#pragma unroll
  for (int g=0; g<4; g++){
    float s0=x[g*4+0]*x[g*4+0], s1=x[g*4+1]*x[g*4+1],
          s2=x[g*4+2]*x[g*4+2], s3=x[g*4+3]*x[g*4+3];
    warpSum4(s0,s1,s2,s3);
    if (lane==0){ part[rl0+g*4+0][half]=s0; part[rl0+g*4+1][half]=s1;
                  part[rl0+g*4+2][half]=s2; part[rl0+g*4+3][half]=s3; }
  }
  __syncthreads();
  float gd = lng[d], bd = lnb[d], wd = wi_w[d];
  float wl[16];
#pragma unroll
  for (int j=0;j<16;j++){
    float var = (part[rl0+j][0]+part[rl0+j][1])*(1.f/64.f);
    float xn = x[j]*rsqrtf(var+1e-5f)*gd + bd;
    xsT[d][rl0+j] = xn;
    g_xn[(size_t)(row0+j)*DD + d] = xn;
    wl[j] = xn*wd;
  }
  __syncthreads();
  /* input-marginal logits */
#pragma unroll
  for (int g=0; g<4; g++){
    float s0=wl[g*4+0], s1=wl[g*4+1], s2=wl[g*4+2], s3=wl[g*4+3];
    warpSum4(s0,s1,s2,s3);
    if (lane==0){ part[rl0+g*4+0][half]=s0; part[rl0+g*4+1][half]=s1;
                  part[rl0+g*4+2][half]=s2; part[rl0+g*4+3][half]=s3; }
  }
  __syncthreads();
  if (tid < 64) g_wilogit[blockIdx.x*64 + tid] = part[tid][0]+part[tid][1] + wi_b[0];
  __syncthreads();

  /* ---- k = xn @ Wk (16 rows per thread, FFMA2 pairs) ---- */
  float2 acc[8];
#pragma unroll
  for (int r2=0;r2<8;r2++) acc[r2] = make_float2(0.f,0.f);
#pragma unroll
  for (int e4=0;e4<16;e4++){
    float4 w4 = *(const float4*)&WkT[d][e4*4];
#pragma unroll
    for (int jj=0;jj<4;jj++){
      float wj = (jj==0)?w4.x:(jj==1)?w4.y:(jj==2)?w4.z:w4.w;
      float2 wdup = make_float2(wj, wj);
      int e = e4*4+jj;
#pragma unroll
      for (int r4=0;r4<4;r4++){
        float4 x4 = *(const float4*)&xsT[e][rl0 + r4*4];
        acc[r4*2+0] = ffma2(make_float2(x4.x,x4.y), wdup, acc[r4*2+0]);
        acc[r4*2+1] = ffma2(make_float2(x4.z,x4.w), wdup, acc[r4*2+1]);
      }
    }
  }
  float kk[16];
#pragma unroll
  for (int r2=0;r2<8;r2++){ kk[r2*2]=acc[r2].x; kk[r2*2+1]=acc[r2].y; }
#pragma unroll
  for (int j=0;j<16;j++) g_k[(size_t)(row0+j)*DD + d] = kk[j];

  /* ksq */
#pragma unroll
  for (int g=0; g<4; g++){
    float s0=kk[g*4+0]*kk[g*4+0], s1=kk[g*4+1]*kk[g*4+1],
          s2=kk[g*4+2]*kk[g*4+2], s3=kk[g*4+3]*kk[g*4+3];
    warpSum4(s0,s1,s2,s3);
    if (lane==0){ part[rl0+g*4+0][half]=s0; part[rl0+g*4+1][half]=s1;
                  part[rl0+g*4+2][half]=s2; part[rl0+g*4+3][half]=s3; }
  }
  __syncthreads();
  if (tid < 64) g_ksq[blockIdx.x*64 + tid] = part[tid][0]+part[tid][1];
}

/* ------------- sinkhorn: 512 thr, 2 rows/thr, 2 CTAs/SM ----------------- */
template<class F>
__device__ __forceinline__ void colSumApply(const float* vals, float (*xp)[HT],
                                            int i, int warp, int lane, F f)
{
#pragma unroll
  for (int j=0;j<SS;j++) xp[j][i] = vals[j];
  __syncthreads();
  if (warp < SS){
    const float4* row = (const float4*)xp[warp];
    float s = 0.f;
#pragma unroll
    for (int q4=0;q4<4;q4++){
      float4 a = row[lane + q4*32];
      s += (a.x+a.y)+(a.z+a.w);
    }
    s = warpSum(s);
    if (lane==0) f(warp, s);
  }
  __syncthreads();
}

__global__ void __launch_bounds__(HT, 2) sinkhorn_kernel(float* __restrict__ attn)
{
  int b = blockIdx.x;
  int i = threadIdx.x;               /* rows i and i+512 */
  int lane = i&31, warp = i>>5;

  __shared__ float xpose[SS][HT];          /* aliases qT at start */
  __shared__ float euh_s[SHI][2][HT];
  __shared__ float evh[SHI+1][SS];
  __shared__ float dv_sh[SS];
  __shared__ float eb_sh[SS];
  __shared__ float binv_sh[SS];
  __shared__ float evcur[SS];
  __shared__ float qsq_sh[SS];
  __shared__ float red[16];
  __shared__ float bcast;

  float* qT = &xpose[0][0];                /* [64][12] = 768 floats */
  for (int idx=i; idx<SS*DD; idx+=HT){
    int sj=idx>>6, e=idx&63;
    qT[e*12+sj] = g_q[((size_t)b*SS+sj)*DD + e];
  }
  if (i < SS){
    float lb = g_logb[b*SS+i];
    eb_sh[i]   = __expf(lb);
    binv_sh[i] = __expf(-lb);
    evcur[i]   = 1.f;
    qsq_sh[i]  = g_qsq[b*SS+i];
  }
  __syncthreads();

  /* K = exp(-dist), two rows */
  float K0[SS], K1[SS];
  {
    float d0[SS], d1[SS];
#pragma unroll
    for (int j=0;j<SS;j++){ d0[j]=0.f; d1[j]=0.f; }
    const float4* kr0 = (const float4*)(g_k + ((size_t)b*NN + i)*DD);
    const float4* kr1 = (const float4*)(g_k + ((size_t)b*NN + i + HT)*DD);
#pragma unroll
    for (int e4=0;e4<16;e4++){
      float4 a = kr0[e4];
      float4 c = kr1[e4];
      int e = e4*4;
#pragma unroll
      for (int j=0;j<SS;j++){
        d0[j]=fmaf(a.x, qT[(e+0)*12+j], d0[j]);
        d0[j]=fmaf(a.y, qT[(e+1)*12+j], d0[j]);
        d0[j]=fmaf(a.z, qT[(e+2)*12+j], d0[j]);
        d0[j]=fmaf(a.w, qT[(e+3)*12+j], d0[j]);
        d1[j]=fmaf(c.x, qT[(e+0)*12+j], d1[j]);
        d1[j]=fmaf(c.y, qT[(e+1)*12+j], d1[j]);
        d1[j]=fmaf(c.z, qT[(e+2)*12+j], d1[j]);
        d1[j]=fmaf(c.w, qT[(e+3)*12+j], d1[j]);
      }
    }
    float ks0 = g_ksq[b*NN+i];
    float ks1 = g_ksq[b*NN+i+HT];
#pragma unroll
    for (int j=0;j<SS;j++){
      float q2 = qsq_sh[j];
      K0[j] = __expf(-sqrtf(fmaxf(ks0 + q2 - 2.f*d0[j], 1e-12f)));
      K1[j] = __expf(-sqrtf(fmaxf(ks1 + q2 - 2.f*d1[j], 1e-12f)));
    }
  }

  /* a = 11*softmax(wilogit), fused */
  float a0, a1, ainv0, ainv1;
  {
    float l0 = g_wilogit[b*NN+i];
    float l1 = g_wilogit[b*NN+i+HT];
    float m = warpMax(fmaxf(l0,l1));
    if (lane==0) red[warp]=m;
    __syncthreads();
    if (warp==0){ float x = (lane<16)? red[lane] : -1e30f; x=warpMax(x); if(lane==0) bcast=x; }
    __syncthreads();
    float M = bcast;
    __syncthreads();
    float e0 = __expf(l0-M), e1 = __expf(l1-M);
    float sv = warpSum(e0+e1);
    if (lane==0) red[warp]=sv;
    __syncthreads();
    if (warp==0){ float x = (lane<16)? red[lane] : 0.f; x=warpSum(x); if(lane==0) bcast=x; }
    __syncthreads();
    float S = bcast;
    a0 = __fdividef(11.f*e0, S);  ainv0 = __fdividef(S, 11.f*e0);
    a1 = __fdividef(11.f*e1, S);  ainv1 = __fdividef(S, 11.f*e1);
    __syncthreads();
  }

  for (int mi=0; mi<MESHI; mi++){
    if (i<SS) evh[0][i]=evcur[i];
    __syncthreads();

#pragma unroll
    for (int t=1;t<=SHI;t++){
      float s0=0.f, s1=0.f;
#pragma unroll
      for (int j=0;j<SS;j++){
        float ev = evcur[j];
        s0 = fmaf(K0[j], ev, s0);
        s1 = fmaf(K1[j], ev, s1);
      }
      float eu0 = __fdividef(a0, s0);
      float eu1 = __fdividef(a1, s1);
      euh_s[t-1][0][i]=eu0;
      euh_s[t-1][1][i]=eu1;
      float cv[SS];
#pragma unroll
      for (int j=0;j<SS;j++) cv[j] = K0[j]*eu0 + K1[j]*eu1;
      colSumApply(cv, xpose, i, warp, lane, [&](int j, float sv){
        float nv = __fdividef(eb_sh[j], sv);
        evcur[j]=nv; evh[t][j]=nv;
      });
    }

    float dp0[SS], dp1[SS];
    float du50=0.f, du51=0.f;
    {
      float dvv[SS];
      float eu50 = euh_s[SHI-1][0][i];
      float eu51 = euh_s[SHI-1][1][i];
#pragma unroll
      for (int j=0;j<SS;j++){
        float ev5 = evcur[j];
        float T0 = K0[j]*eu50*ev5;
        float T1 = K1[j]*eu51*ev5;
        float Tp0 = T0 + 1e-8f, Tp1 = T1 + 1e-8f;
        float dz0 = -(__logf(Tp0) + __fdividef(T0,Tp0))*T0;
        float dz1 = -(__logf(Tp1) + __fdividef(T1,Tp1))*T1;
        dp0[j]=dz0; dp1[j]=dz1;
        du50+=dz0; du51+=dz1;
        dvv[j]=dz0+dz1;
      }
      colSumApply(dvv, xpose, i, warp, lane, [&](int j, float s){ dv_sh[j]=s; });
    }
#pragma unroll
    for (int t=SHI; t>=1; t--){
      float eut0 = euh_s[t-1][0][i];
      float eut1 = euh_s[t-1][1][i];
      float dl0 = (t==SHI) ? du50 : 0.f;
      float dl1 = (t==SHI) ? du51 : 0.f;
#pragma unroll
      for (int j=0;j<SS;j++){
        float wj = evh[t][j]*binv_sh[j];
        float c0 = dv_sh[j]*K0[j]*eut0*wj;
        float c1 = dv_sh[j]*K1[j]*eut1*wj;
        dp0[j] -= c0; dl0 -= c0;
        dp1[j] -= c1; dl1 -= c1;
      }
      float contrib[SS];
      float g0 = dl0*ainv0, g1 = dl1*ainv1;
#pragma unroll
      for (int j=0;j<SS;j++){
        float e2c = evh[t-1][j];
        float mm0 = K0[j]*eut0*e2c*g0;
        float mm1 = K1[j]*eut1*e2c*g1;
        dp0[j] -= mm0;
        dp1[j] -= mm1;
        contrib[j] = -(mm0+mm1);
      }
      if (t>1) colSumApply(contrib, xpose, i, warp, lane, [&](int j, float s){ dv_sh[j]=s; });
    }
#pragma unroll
    for (int j=0;j<SS;j++){
      K0[j] *= __expf(-dp0[j]);
      K1[j] *= __expf(-dp1[j]);
    }
    __syncthreads();
  }

  float eu0=1.f, eu1=1.f;
#pragma unroll
  for (int t=0;t<SHI;t++){
    float s0=0.f, s1=0.f;
#pragma unroll
    for (int j=0;j<SS;j++){
      float ev = evcur[j];
      s0 = fmaf(K0[j], ev, s0);
      s1 = fmaf(K1[j], ev, s1);
    }
    eu0 = __fdividef(a0, s0);
    eu1 = __fdividef(a1, s1);
    float cv[SS];
#pragma unroll
    for (int j=0;j<SS;j++) cv[j] = K0[j]*eu0 + K1[j]*eu1;
    colSumApply(cv, xpose, i, warp, lane, [&](int j, float sv){
      evcur[j] = __fdividef(eb_sh[j], sv);
    });
  }
#pragma unroll
  for (int j=0;j<SS;j++){
    float ev = evcur[j];
    attn[((size_t)b*SS+j)*NN + i]      = K0[j]*eu0*ev;
    attn[((size_t)b*SS+j)*NN + i + HT] = K1[j]*eu1*ev;
  }
}

/* ------------- fused (attn@xn)@Wv + GRU + residual MLP ------------------ */
__global__ void __launch_bounds__(704, 2) update_gru_kernel(
  const float* __restrict__ attn, const float* __restrict__ Wv,
  const float* __restrict__ Wih, const float* __restrict__ Whh,
  const float* __restrict__ bih, const float* __restrict__ bhh,
  const float* __restrict__ fc1w, const float* __restrict__ fc1b,
  const float* __restrict__ fc2w, const float* __restrict__ fc2b,
  const float* __restrict__ lng, const float* __restrict__ lnb,
  float* __restrict__ out_slots)
{
  int b = blockIdx.x;
  int t = threadIdx.x;        /* 0..703 */
  __shared__ float xnT[64][68];     /* transposed xn tile */
  __shared__ float at[11][68];      /* attn tile          */
  __shared__ float praw[11][64];    /* attn @ xn          */
  __shared__ float xsh[11][64], hsh[11][64], ysh[11][64];
  __shared__ float hid[11][128];
  __shared__ float part[11][2];

  /* Phase A: praw = attn @ xn.  Layout: sA = t%11, dA = t/11 (broadcast reuse). */
  int dA = t / 11;
  int sA = t - dA*11;
  const float* xb = g_xn + (size_t)b*NN*DD;
  const float* ab = attn + (size_t)b*SS*NN;
  int sStage = t >> 6, rStage = t & 63;   /* for at staging */
  float2 acc2 = make_float2(0.f, 0.f);

  for (int tile=0; tile<16; tile++){
    int i0 = tile*64;
    for (int idx=t; idx<4096; idx+=704){
      int r = idx>>6, dd = idx&63;
      xnT[dd][r] = xb[(size_t)(i0+r)*DD + dd];
    }
    at[sStage][rStage] = ab[(size_t)sStage*NN + i0 + rStage];
    __syncthreads();
#pragma unroll
    for (int ii4=0; ii4<16; ii4++){
      float4 x4 = *(const float4*)&xnT[dA][ii4*4];
      float4 a4 = *(const float4*)&at[sA][ii4*4];
      acc2 = ffma2(make_float2(a4.x,a4.y), make_float2(x4.x,x4.y), acc2);
      acc2 = ffma2(make_float2(a4.z,a4.w), make_float2(x4.z,x4.w), acc2);
    }
    __syncthreads();
  }
  praw[sA][dA] = acc2.x + acc2.y;
  __syncthreads();

  /* Phase A2: updates = praw @ Wv  (Phase-B layout) */
  int sI = t>>6, d = t&63;
  int lane = d&31, half = d>>5;
  float upd = 0.f;
#pragma unroll 8
  for (int e=0;e<64;e++) upd = fmaf(praw[sI][e], Wv[e*64+d], upd);

  /* Phase B: GRU + LN + MLP */
  int row = b*SS + sI;
  xsh[sI][d] = upd;
  float h = g_slots[row*DD+d];
  hsh[sI][d] = h;
  __syncthreads();

  float gi_r=bih[d], gi_z=bih[64+d], gi_n=bih[128+d];
  float gh_r=bhh[d], gh_z=bhh[64+d], gh_n=bhh[128+d];
#pragma unroll 8
  for (int e=0;e<64;e++){
    float xe=xsh[sI][e], he=hsh[sI][e];
    gi_r=fmaf(xe, Wih[e*192+d],     gi_r);
    gi_z=fmaf(xe, Wih[e*192+64+d],  gi_z);
    gi_n=fmaf(xe, Wih[e*192+128+d], gi_n);
    gh_r=fmaf(he, Whh[e*192+d],     gh_r);
    gh_z=fmaf(he, Whh[e*192+64+d],  gh_z);
    gh_n=fmaf(he, Whh[e*192+128+d], gh_n);
  }
  float r  = 1.f/(1.f+__expf(-(gi_r+gh_r)));
  float z  = 1.f/(1.f+__expf(-(gi_z+gh_z)));
  float ex = __expf(-2.f*(gi_n + r*gh_n));
  float nn = (1.f-ex)/(1.f+ex);
  float hnew = (1.f-z)*nn + z*h;

  float s = warpSum(hnew);
  if (lane==0) part[sI][half]=s;
  __syncthreads();
  float mean=(part[sI][0]+part[sI][1])*(1.f/64.f);
  float c = hnew-mean;
  __syncthreads();
  s = warpSum(c*c);
  if (lane==0) part[sI][half]=s;
  __syncthreads();
  float var=(part[sI][0]+part[sI][1])*(1.f/64.f);
  float y = c*rsqrtf(var+1e-5f)*lng[d]+lnb[d];
  ysh[sI][d]=y;
  __syncthreads();

  float h0=fc1b[d], h1=fc1b[64+d];
#pragma unroll 8
  for (int e=0;e<64;e++){
    float ye=ysh[sI][e];
    h0=fmaf(ye, fc1w[e*128+d],    h0);
    h1=fmaf(ye, fc1w[e*128+64+d], h1);
  }
  hid[sI][d]=fmaxf(h0,0.f); hid[sI][64+d]=fmaxf(h1,0.f);
  __syncthreads();

  float o=fc2b[d];
#pragma unroll 16
  for (int hh=0; hh<128; hh++) o=fmaf(hid[sI][hh], fc2w[hh*64+d], o);
  float outv = hnew + o;
  g_slots[row*DD+d]=outv;
  out_slots[row*DD+d]=outv;
}

/* ------------------------------- launcher ------------------------------- */
extern "C" void kernel_launch(void* const* d_in, const int* in_sizes, int n_in,
                              void* d_out, int out_size)
{
  const float* inputs          = (const float*)d_in[0];
  const float* slots_init      = (const float*)d_in[1];
  const float* slots_mu        = (const float*)d_in[2];
  const float* slots_log_sigma = (const float*)d_in[3];
  const float* Wq      = (const float*)d_in[4];
  const float* Wk      = (const float*)d_in[5];
  const float* Wv      = (const float*)d_in[6];
  const float* gru_Wih = (const float*)d_in[7];
  const float* gru_Whh = (const float*)d_in[8];
  const float* gru_bih = (const float*)d_in[9];
  const float* gru_bhh = (const float*)d_in[10];
  const float* fc1_w   = (const float*)d_in[11];
  const float* fc1_b   = (const float*)d_in[12];
  const float* fc2_w   = (const float*)d_in[13];
  const float* fc2_b   = (const float*)d_in[14];
  const float* ln_in_g = (const float*)d_in[15];
  const float* ln_in_b = (const float*)d_in[16];
  const float* ln_sl_g = (const float*)d_in[17];
  const float* ln_sl_b = (const float*)d_in[18];
  const float* ln_ff_g = (const float*)d_in[19];
  const float* ln_ff_b = (const float*)d_in[20];
  const float* wi_w    = (const float*)d_in[21];
  const float* wi_b    = (const float*)d_in[22];
  const float* ws_w    = (const float*)d_in[23];
  const float* ws_b    = (const float*)d_in[24];

  float* out       = (float*)d_out;
  float* out_slots = out;                      /* (B,S,D)  */
  float* out_attn  = out + BB*SS*DD;           /* (B,S,N)  */

  slots_init_kernel<<<(BB*SS*DD+255)/256, 256>>>(slots_init, slots_mu, slots_log_sigma);
  slotsnorm_kernel<<<BB, dim3(64,11)>>>(Wq, ln_sl_g, ln_sl_b, ws_w, ws_b);
  preprocess_kernel<<<BB*NN/64, 256>>>(inputs, Wk, ln_in_g, ln_in_b, wi_w, wi_b);

  for (int it=0; it<NITERS; it++){
    if (it > 0)
      slotsnorm_kernel<<<BB, dim3(64,11)>>>(Wq, ln_sl_g, ln_sl_b, ws_w, ws_b);
    sinkhorn_kernel<<<BB, HT>>>(out_attn);
    update_gru_kernel<<<BB, 704>>>(out_attn, Wv, gru_Wih, gru_Whh, gru_bih, gru_bhh,
                                   fc1_w, fc1_b, fc2_w, fc2_b,
                                   ln_ff_g, ln_ff_b, out_slots);
  }
  (void)in_sizes; (void)n_in; (void)out_size;
}

// round 10
// speedup vs baseline: 1.1363x; 1.1363x over previous
#include <cuda_runtime.h>
#include <math.h>

#define BB 256
#define NN 1024
#define SS 11
#define DD 64
#define HHID 128
#define NITERS 3
#define MESHI 4
#define SHI 5
#define HT 512   /* sinkhorn threads; 2 rows each */

/* ---------------- scratch (device globals: no runtime allocation) ------- */
__device__ float g_xn[BB*NN*DD];
__device__ float g_ksq[BB*NN];
__device__ float g_wilogit[BB*NN];
__device__ float g_slots[BB*SS*DD];
__device__ float g_qk[BB*SS*DD];   /* Wk @ q, per slot */
__device__ float g_qsq[BB*SS];
__device__ float g_logb[BB*SS];

/* ---------------- helpers ---------------- */
__device__ __forceinline__ float warpSum(float v){
#pragma unroll
  for (int o=16;o>0;o>>=1) v += __shfl_down_sync(0xffffffffu, v, o);
  return v;
}
__device__ __forceinline__ float warpMax(float v){
#pragma unroll
  for (int o=16;o>0;o>>=1) v = fmaxf(v, __shfl_down_sync(0xffffffffu, v, o));
  return v;
}
__device__ __forceinline__ void warpSum4(float&a,float&b,float&c,float&d){
#pragma unroll
  for (int o=16;o>0;o>>=1){
    a += __shfl_down_sync(0xffffffffu, a, o);
    b += __shfl_down_sync(0xffffffffu, b, o);
    c += __shfl_down_sync(0xffffffffu, c, o);
    d += __shfl_down_sync(0xffffffffu, d, o);
  }
}

/* ------------- kernel: slots = mu + exp(log_sigma)*init ----------------- */
__global__ void slots_init_kernel(const float* __restrict__ sinit,
  const float* __restrict__ mu, const float* __restrict__ lsig)
{
  int idx = blockIdx.x*256 + threadIdx.x;
  if (idx < BB*SS*DD){
    int d = idx & 63;
    g_slots[idx] = mu[d] + expf(lsig[d]) * sinit[idx];
  }
}

/* ------------- slotsnorm: sn=LN(slots), q, qk=Wk@q, qsq, log_b ---------- */
__global__ void slotsnorm_kernel(const float* __restrict__ Wq,
   const float* __restrict__ Wk,
   const float* __restrict__ lng, const float* __restrict__ lnb,
   const float* __restrict__ ws_w, const float* __restrict__ ws_b)
{
  int b = blockIdx.x;
  int sI = threadIdx.y;  /* 0..10 */
  int d  = threadIdx.x;  /* 0..63 */
  int lane = d&31, half = d>>5;
  __shared__ float sn[11][64];
  __shared__ float qsh[11][64];
  __shared__ float part[11][2];
  __shared__ float lg[11];
  int row = b*SS + sI;

  float x = g_slots[row*DD + d];
  float s = warpSum(x);
  if (lane==0) part[sI][half]=s;
  __syncthreads();
  float mean = (part[sI][0]+part[sI][1])*(1.f/64.f);
  float c = x-mean;
  __syncthreads();
  s = warpSum(c*c);
  if (lane==0) part[sI][half]=s;
  __syncthreads();
  float var=(part[sI][0]+part[sI][1])*(1.f/64.f);
  float v = c*rsqrtf(var+1e-5f)*lng[d]+lnb[d];
  sn[sI][d]=v;
  __syncthreads();

  s = warpSum(v*ws_w[d]);
  if (lane==0) part[sI][half]=s;
  __syncthreads();
  if (d==0) lg[sI] = part[sI][0]+part[sI][1] + ws_b[0];

  float qa=0.f;
#pragma unroll 16
  for (int e=0;e<64;e++) qa = fmaf(sn[sI][e], Wq[e*64+d], qa);
  qsh[sI][d]=qa;
  __syncthreads();
  s = warpSum(qa*qa);
  if (lane==0) part[sI][half]=s;
  __syncthreads();
  if (d==0) g_qsq[row]=part[sI][0]+part[sI][1];

  /* qk[sI][e=d] = sum_dd Wk[d][dd] * q[sI][dd]  (Wk row contiguous) */
  {
    const float4* wk4 = (const float4*)(Wk + d*64);
    const float4* q4  = (const float4*)(qsh[sI]);
    float acc=0.f;
#pragma unroll
    for (int e4=0;e4<16;e4++){
      float4 w = wk4[e4], q = q4[e4];
      acc += w.x*q.x + w.y*q.y + w.z*q.z + w.w*q.w;
    }
    g_qk[row*DD + d] = acc;
  }

  if (sI==0 && d==0){
    float M=lg[0];
#pragma unroll
    for (int j=1;j<11;j++) M=fmaxf(M,lg[j]);
    float ss=0.f;
#pragma unroll
    for (int j=0;j<11;j++) ss+=expf(lg[j]-M);
    float lse=M+logf(ss);
#pragma unroll
    for (int j=0;j<11;j++) g_logb[b*SS+j]=lg[j]-lse+2.3978952727983707f;
  }
}

/* ------------- preprocess: LN(inputs)->xn, ksq=|xn@Wk|^2, wi logits ----- */
/* round-8 structure: 4 rows/thread, dim3(64,4), 16 rows/block.            */
__global__ void preprocess_kernel(const float* __restrict__ inp,
    const float* __restrict__ Wk,
    const float* __restrict__ lng, const float* __restrict__ lnb,
    const float* __restrict__ wi_w, const float* __restrict__ wi_b)
{
  int ty = threadIdx.y;                 /* 0..3 */
  int d  = threadIdx.x;                 /* 0..63 */
  int lane = d & 31, half = d >> 5;
  int r0 = blockIdx.x*16 + ty*4;
  __shared__ float xs[16][64];
  __shared__ float part[16][2];

  float x0 = inp[(size_t)(r0+0)*DD + d];
  float x1 = inp[(size_t)(r0+1)*DD + d];
  float x2 = inp[(size_t)(r0+2)*DD + d];
  float x3 = inp[(size_t)(r0+3)*DD + d];

  float s0=x0,s1=x1,s2=x2,s3=x3;
  warpSum4(s0,s1,s2,s3);
  if (lane==0){ part[ty*4+0][half]=s0; part[ty*4+1][half]=s1;
                part[ty*4+2][half]=s2; part[ty*4+3][half]=s3; }
  __syncthreads();
  float c0 = x0 - (part[ty*4+0][0]+part[ty*4+0][1])*(1.f/64.f);
  float c1 = x1 - (part[ty*4+1][0]+part[ty*4+1][1])*(1.f/64.f);
  float c2 = x2 - (part[ty*4+2][0]+part[ty*4+2][1])*(1.f/64.f);
  float c3 = x3 - (part[ty*4+3][0]+part[ty*4+3][1])*(1.f/64.f);
  __syncthreads();
  s0=c0*c0; s1=c1*c1; s2=c2*c2; s3=c3*c3;
  warpSum4(s0,s1,s2,s3);
  if (lane==0){ part[ty*4+0][half]=s0; part[ty*4+1][half]=s1;
                part[ty*4+2][half]=s2; part[ty*4+3][half]=s3; }
  __syncthreads();
  float gd = lng[d], bd = lnb[d];
  float xn0 = c0*rsqrtf((part[ty*4+0][0]+part[ty*4+0][1])*(1.f/64.f)+1e-5f)*gd+bd;
  float xn1 = c1*rsqrtf((part[ty*4+1][0]+part[ty*4+1][1])*(1.f/64.f)+1e-5f)*gd+bd;
  float xn2 = c2*rsqrtf((part[ty*4+2][0]+part[ty*4+2][1])*(1.f/64.f)+1e-5f)*gd+bd;
  float xn3 = c3*rsqrtf((part[ty*4+3][0]+part[ty*4+3][1])*(1.f/64.f)+1e-5f)*gd+bd;
  xs[ty*4+0][d]=xn0; xs[ty*4+1][d]=xn1; xs[ty*4+2][d]=xn2; xs[ty*4+3][d]=xn3;
  g_xn[(size_t)(r0+0)*DD+d]=xn0;
  g_xn[(size_t)(r0+1)*DD+d]=xn1;
  g_xn[(size_t)(r0+2)*DD+d]=xn2;
  g_xn[(size_t)(r0+3)*DD+d]=xn3;
  __syncthreads();

  /* k rows (internal only, for ksq) */
  float ka0=0.f,ka1=0.f,ka2=0.f,ka3=0.f;
#pragma unroll 8
  for (int e=0;e<64;e++){
    float wk = Wk[e*64+d];
    ka0 = fmaf(xs[ty*4+0][e],wk,ka0);
    ka1 = fmaf(xs[ty*4+1][e],wk,ka1);
    ka2 = fmaf(xs[ty*4+2][e],wk,ka2);
    ka3 = fmaf(xs[ty*4+3][e],wk,ka3);
  }
  __syncthreads();
  s0=ka0*ka0; s1=ka1*ka1; s2=ka2*ka2; s3=ka3*ka3;
  warpSum4(s0,s1,s2,s3);
  if (lane==0){ part[ty*4+0][half]=s0; part[ty*4+1][half]=s1;
                part[ty*4+2][half]=s2; part[ty*4+3][half]=s3; }
  __syncthreads();
  if (d<4) g_ksq[r0 + d] = part[ty*4+d][0]+part[ty*4+d][1];
  __syncthreads();
  float wd = wi_w[d];
  s0=xn0*wd; s1=xn1*wd; s2=xn2*wd; s3=xn3*wd;
  warpSum4(s0,s1,s2,s3);
  if (lane==0){ part[ty*4+0][half]=s0; part[ty*4+1][half]=s1;
                part[ty*4+2][half]=s2; part[ty*4+3][half]=s3; }
  __syncthreads();
  if (d<4) g_wilogit[r0 + d] = part[ty*4+d][0]+part[ty*4+d][1] + wi_b[0];
}

/* ------------- sinkhorn: 512 thr, 2 rows/thr, 2 CTAs/SM ----------------- */
template<class F>
__device__ __forceinline__ void colSumApply(const float* vals, float (*xp)[HT],
                                            int i, int warp, int lane, F f)
{
#pragma unroll
  for (int j=0;j<SS;j++) xp[j][i] = vals[j];
  __syncthreads();
  if (warp < SS){
    const float4* row = (const float4*)xp[warp];
    float s = 0.f;
#pragma unroll
    for (int q4=0;q4<4;q4++){
      float4 a = row[lane + q4*32];
      s += (a.x+a.y)+(a.z+a.w);
    }
    s = warpSum(s);
    if (lane==0) f(warp, s);
  }
  __syncthreads();
}

__global__ void __launch_bounds__(HT, 2) sinkhorn_kernel(float* __restrict__ attn)
{
  int b = blockIdx.x;
  int i = threadIdx.x;               /* rows i and i+512 */
  int lane = i&31, warp = i>>5;

  __shared__ float xpose[SS][HT];          /* aliases qT at start */
  __shared__ float euh_s[SHI][2][HT];
  __shared__ float evh[SHI+1][SS];
  __shared__ float dv_sh[SS];
  __shared__ float eb_sh[SS];
  __shared__ float binv_sh[SS];
  __shared__ float evcur[SS];
  __shared__ float qsq_sh[SS];
  __shared__ float red[16];
  __shared__ float bcast;

  float* qT = &xpose[0][0];                /* [64][12] = 768 floats */
  for (int idx=i; idx<SS*DD; idx+=HT){
    int sj=idx>>6, e=idx&63;
    qT[e*12+sj] = g_qk[((size_t)b*SS+sj)*DD + e];
  }
  if (i < SS){
    float lb = g_logb[b*SS+i];
    eb_sh[i]   = __expf(lb);
    binv_sh[i] = __expf(-lb);
    evcur[i]   = 1.f;
    qsq_sh[i]  = g_qsq[b*SS+i];
  }
  __syncthreads();

  /* K = exp(-dist), two rows; dot = xn . (Wk q) */
  float K0[SS], K1[SS];
  {
    float d0[SS], d1[SS];
#pragma unroll
    for (int j=0;j<SS;j++){ d0[j]=0.f; d1[j]=0.f; }
    const float4* kr0 = (const float4*)(g_xn + ((size_t)b*NN + i)*DD);
    const float4* kr1 = (const float4*)(g_xn + ((size_t)b*NN + i + HT)*DD);
#pragma unroll
    for (int e4=0;e4<16;e4++){
      float4 a = kr0[e4];
      float4 c = kr1[e4];
      int e = e4*4;
#pragma unroll
      for (int j=0;j<SS;j++){
        d0[j]=fmaf(a.x, qT[(e+0)*12+j], d0[j]);
        d0[j]=fmaf(a.y, qT[(e+1)*12+j], d0[j]);
        d0[j]=fmaf(a.z, qT[(e+2)*12+j], d0[j]);
        d0[j]=fmaf(a.w, qT[(e+3)*12+j], d0[j]);
        d1[j]=fmaf(c.x, qT[(e+0)*12+j], d1[j]);
        d1[j]=fmaf(c.y, qT[(e+1)*12+j], d1[j]);
        d1[j]=fmaf(c.z, qT[(e+2)*12+j], d1[j]);
        d1[j]=fmaf(c.w, qT[(e+3)*12+j], d1[j]);
      }
    }
    float ks0 = g_ksq[b*NN+i];
    float ks1 = g_ksq[b*NN+i+HT];
#pragma unroll
    for (int j=0;j<SS;j++){
      float q2 = qsq_sh[j];
      K0[j] = __expf(-sqrtf(fmaxf(ks0 + q2 - 2.f*d0[j], 1e-12f)));
      K1[j] = __expf(-sqrtf(fmaxf(ks1 + q2 - 2.f*d1[j], 1e-12f)));
    }
  }

  /* a = 11*softmax(wilogit), fused */
  float a0, a1, ainv0, ainv1;
  {
    float l0 = g_wilogit[b*NN+i];
    float l1 = g_wilogit[b*NN+i+HT];
    float m = warpMax(fmaxf(l0,l1));
    if (lane==0) red[warp]=m;
    __syncthreads();
    if (warp==0){ float x = (lane<16)? red[lane] : -1e30f; x=warpMax(x); if(lane==0) bcast=x; }
    __syncthreads();
    float M = bcast;
    __syncthreads();
    float e0 = __expf(l0-M), e1 = __expf(l1-M);
    float sv = warpSum(e0+e1);
    if (lane==0) red[warp]=sv;
    __syncthreads();
    if (warp==0){ float x = (lane<16)? red[lane] : 0.f; x=warpSum(x); if(lane==0) bcast=x; }
    __syncthreads();
    float S = bcast;
    a0 = __fdividef(11.f*e0, S);  ainv0 = __fdividef(S, 11.f*e0);
    a1 = __fdividef(11.f*e1, S);  ainv1 = __fdividef(S, 11.f*e1);
    __syncthreads();
  }

  for (int mi=0; mi<MESHI; mi++){
    if (i<SS) evh[0][i]=evcur[i];
    __syncthreads();

#pragma unroll
    for (int t=1;t<=SHI;t++){
      float s0=0.f, s1=0.f;
#pragma unroll
      for (int j=0;j<SS;j++){
        float ev = evcur[j];
        s0 = fmaf(K0[j], ev, s0);
        s1 = fmaf(K1[j], ev, s1);
      }
      float eu0 = __fdividef(a0, s0);
      float eu1 = __fdividef(a1, s1);
      euh_s[t-1][0][i]=eu0;
      euh_s[t-1][1][i]=eu1;
      float cv[SS];
#pragma unroll
      for (int j=0;j<SS;j++) cv[j] = K0[j]*eu0 + K1[j]*eu1;
      colSumApply(cv, xpose, i, warp, lane, [&](int j, float sv){
        float nv = __fdividef(eb_sh[j], sv);
        evcur[j]=nv; evh[t][j]=nv;
      });
    }

    float dp0[SS], dp1[SS];
    float du50=0.f, du51=0.f;
    {
      float dvv[SS];
      float eu50 = euh_s[SHI-1][0][i];
      float eu51 = euh_s[SHI-1][1][i];
#pragma unroll
      for (int j=0;j<SS;j++){
        float ev5 = evcur[j];
        float T0 = K0[j]*eu50*ev5;
        float T1 = K1[j]*eu51*ev5;
        float Tp0 = T0 + 1e-8f, Tp1 = T1 + 1e-8f;
        float dz0 = -(__logf(Tp0) + __fdividef(T0,Tp0))*T0;
        float dz1 = -(__logf(Tp1) + __fdividef(T1,Tp1))*T1;
        dp0[j]=dz0; dp1[j]=dz1;
        du50+=dz0; du51+=dz1;
        dvv[j]=dz0+dz1;
      }
      colSumApply(dvv, xpose, i, warp, lane, [&](int j, float s){ dv_sh[j]=s; });
    }
#pragma unroll
    for (int t=SHI; t>=1; t--){
      float eut0 = euh_s[t-1][0][i];
      float eut1 = euh_s[t-1][1][i];
      float dl0 = (t==SHI) ? du50 : 0.f;
      float dl1 = (t==SHI) ? du51 : 0.f;
#pragma unroll
      for (int j=0;j<SS;j++){
        float wj = evh[t][j]*binv_sh[j];
        float c0 = dv_sh[j]*K0[j]*eut0*wj;
        float c1 = dv_sh[j]*K1[j]*eut1*wj;
        dp0[j] -= c0; dl0 -= c0;
        dp1[j] -= c1; dl1 -= c1;
      }
      float contrib[SS];
      float g0 = dl0*ainv0, g1 = dl1*ainv1;
#pragma unroll
      for (int j=0;j<SS;j++){
        float e2c = evh[t-1][j];
        float mm0 = K0[j]*eut0*e2c*g0;
        float mm1 = K1[j]*eut1*e2c*g1;
        dp0[j] -= mm0;
        dp1[j] -= mm1;
        contrib[j] = -(mm0+mm1);
      }
      if (t>1) colSumApply(contrib, xpose, i, warp, lane, [&](int j, float s){ dv_sh[j]=s; });
    }
#pragma unroll
    for (int j=0;j<SS;j++){
      K0[j] *= __expf(-dp0[j]);
      K1[j] *= __expf(-dp1[j]);
    }
    __syncthreads();
  }

  float eu0=1.f, eu1=1.f;
#pragma unroll
  for (int t=0;t<SHI;t++){
    float s0=0.f, s1=0.f;
#pragma unroll
    for (int j=0;j<SS;j++){
      float ev = evcur[j];
      s0 = fmaf(K0[j], ev, s0);
      s1 = fmaf(K1[j], ev, s1);
    }
    eu0 = __fdividef(a0, s0);
    eu1 = __fdividef(a1, s1);
    float cv[SS];
#pragma unroll
    for (int j=0;j<SS;j++) cv[j] = K0[j]*eu0 + K1[j]*eu1;
    colSumApply(cv, xpose, i, warp, lane, [&](int j, float sv){
      evcur[j] = __fdividef(eb_sh[j], sv);
    });
  }
#pragma unroll
  for (int j=0;j<SS;j++){
    float ev = evcur[j];
    attn[((size_t)b*SS+j)*NN + i]      = K0[j]*eu0*ev;
    attn[((size_t)b*SS+j)*NN + i + HT] = K1[j]*eu1*ev;
  }
}

/* ------------- fused (attn@xn)@Wv + GRU + residual MLP ------------------ */
__global__ void __launch_bounds__(704, 2) update_gru_kernel(
  const float* __restrict__ attn, const float* __restrict__ Wv,
  const float* __restrict__ Wih, const float* __restrict__ Whh,
  const float* __restrict__ bih, const float* __restrict__ bhh,
  const float* __restrict__ fc1w, const float* __restrict__ fc1b,
  const float* __restrict__ fc2w, const float* __restrict__ fc2b,
  const float* __restrict__ lng, const float* __restrict__ lnb,
  float* __restrict__ out_slots)
{
  int b = blockIdx.x;
  int t = threadIdx.x;        /* 0..703 */
  int sI = t>>6, d = t&63;
  int lane = d&31, half = d>>5;
  __shared__ float vt[64][64];
  __shared__ float at[11][64];
  __shared__ float praw[11][64];
  __shared__ float xsh[11][64], hsh[11][64], ysh[11][64];
  __shared__ float hid[11][128];
  __shared__ float part[11][2];

  /* Phase A: praw = attn @ xn  (round-8 tiling) */
  const float* xb = g_xn + (size_t)b*NN*DD;
  const float* ab = attn + (size_t)b*SS*NN;
  float acc=0.f;
  for (int tile=0; tile<16; tile++){
    int i0 = tile*64;
    for (int idx=t; idx<4096; idx+=704)
      ((float*)vt)[idx] = xb[(size_t)i0*DD + idx];
    at[sI][d] = ab[(size_t)sI*NN + i0 + d];
    __syncthreads();
#pragma unroll 16
    for (int ii=0; ii<64; ii++)
      acc = fmaf(at[sI][ii], vt[ii][d], acc);
    __syncthreads();
  }
  praw[sI][d] = acc;
  __syncthreads();

  /* Phase A2: updates = praw @ Wv */
  float upd = 0.f;
#pragma unroll 8
  for (int e=0;e<64;e++) upd = fmaf(praw[sI][e], Wv[e*64+d], upd);

  /* Phase B: GRU + LN + MLP */
  int row = b*SS + sI;
  xsh[sI][d] = upd;
  float h = g_slots[row*DD+d];
  hsh[sI][d] = h;
  __syncthreads();

  float gi_r=bih[d], gi_z=bih[64+d], gi_n=bih[128+d];
  float gh_r=bhh[d], gh_z=bhh[64+d], gh_n=bhh[128+d];
#pragma unroll 8
  for (int e=0;e<64;e++){
    float xe=xsh[sI][e], he=hsh[sI][e];
    gi_r=fmaf(xe, Wih[e*192+d],     gi_r);
    gi_z=fmaf(xe, Wih[e*192+64+d],  gi_z);
    gi_n=fmaf(xe, Wih[e*192+128+d], gi_n);
    gh_r=fmaf(he, Whh[e*192+d],     gh_r);
    gh_z=fmaf(he, Whh[e*192+64+d],  gh_z);
    gh_n=fmaf(he, Whh[e*192+128+d], gh_n);
  }
  float r  = 1.f/(1.f+__expf(-(gi_r+gh_r)));
  float z  = 1.f/(1.f+__expf(-(gi_z+gh_z)));
  float ex = __expf(-2.f*(gi_n + r*gh_n));
  float nn = (1.f-ex)/(1.f+ex);
  float hnew = (1.f-z)*nn + z*h;

  float s = warpSum(hnew);
  if (lane==0) part[sI][half]=s;
  __syncthreads();
  float mean=(part[sI][0]+part[sI][1])*(1.f/64.f);
  float c = hnew-mean;
  __syncthreads();
  s = warpSum(c*c);
  if (lane==0) part[sI][half]=s;
  __syncthreads();
  float var=(part[sI][0]+part[sI][1])*(1.f/64.f);
  float y = c*rsqrtf(var+1e-5f)*lng[d]+lnb[d];
  ysh[sI][d]=y;
  __syncthreads();

  float h0=fc1b[d], h1=fc1b[64+d];
#pragma unroll 8
  for (int e=0;e<64;e++){
    float ye=ysh[sI][e];
    h0=fmaf(ye, fc1w[e*128+d],    h0);
    h1=fmaf(ye, fc1w[e*128+64+d], h1);
  }
  hid[sI][d]=fmaxf(h0,0.f); hid[sI][64+d]=fmaxf(h1,0.f);
  __syncthreads();

  float o=fc2b[d];
#pragma unroll 16
  for (int hh=0; hh<128; hh++) o=fmaf(hid[sI][hh], fc2w[hh*64+d], o);
  float outv = hnew + o;
  g_slots[row*DD+d]=outv;
  out_slots[row*DD+d]=outv;
}

/* ------------------------------- launcher ------------------------------- */
extern "C" void kernel_launch(void* const* d_in, const int* in_sizes, int n_in,
                              void* d_out, int out_size)
{
  const float* inputs          = (const float*)d_in[0];
  const float* slots_init      = (const float*)d_in[1];
  const float* slots_mu        = (const float*)d_in[2];
  const float* slots_log_sigma = (const float*)d_in[3];
  const float* Wq      = (const float*)d_in[4];
  const float* Wk      = (const float*)d_in[5];
  const float* Wv      = (const float*)d_in[6];
  const float* gru_Wih = (const float*)d_in[7];
  const float* gru_Whh = (const float*)d_in[8];
  const float* gru_bih = (const float*)d_in[9];
  const float* gru_bhh = (const float*)d_in[10];
  const float* fc1_w   = (const float*)d_in[11];
  const float* fc1_b   = (const float*)d_in[12];
  const float* fc2_w   = (const float*)d_in[13];
  const float* fc2_b   = (const float*)d_in[14];
  const float* ln_in_g = (const float*)d_in[15];
  const float* ln_in_b = (const float*)d_in[16];
  const float* ln_sl_g = (const float*)d_in[17];
  const float* ln_sl_b = (const float*)d_in[18];
  const float* ln_ff_g = (const float*)d_in[19];
  const float* ln_ff_b = (const float*)d_in[20];
  const float* wi_w    = (const float*)d_in[21];
  const float* wi_b    = (const float*)d_in[22];
  const float* ws_w    = (const float*)d_in[23];
  const float* ws_b    = (const float*)d_in[24];

  float* out       = (float*)d_out;
  float* out_slots = out;                      /* (B,S,D)  */
  float* out_attn  = out + BB*SS*DD;           /* (B,S,N)  */

  slots_init_kernel<<<(BB*SS*DD+255)/256, 256>>>(slots_init, slots_mu, slots_log_sigma);
  slotsnorm_kernel<<<BB, dim3(64,11)>>>(Wq, Wk, ln_sl_g, ln_sl_b, ws_w, ws_b);
  preprocess_kernel<<<BB*NN/16, dim3(64,4)>>>(inputs, Wk, ln_in_g, ln_in_b, wi_w, wi_b);

  for (int it=0; it<NITERS; it++){
    if (it > 0)
      slotsnorm_kernel<<<BB, dim3(64,11)>>>(Wq, Wk, ln_sl_g, ln_sl_b, ws_w, ws_b);
    sinkhorn_kernel<<<BB, HT>>>(out_attn);
    update_gru_kernel<<<BB, 704>>>(out_attn, Wv, gru_Wih, gru_Whh, gru_bih, gru_bhh,
                                   fc1_w, fc1_b, fc2_w, fc2_b,
                                   ln_ff_g, ln_ff_b, out_slots);
  }
  (void)in_sizes; (void)n_in; (void)out_size;
}

// round 11
// speedup vs baseline: 1.3583x; 1.1954x over previous
#include <cuda_runtime.h>
#include <math.h>

#define BB 256
#define NN 1024
#define SS 11
#define DD 64
#define HHID 128
#define NITERS 3
#define MESHI 4
#define SHI 5
#define HT 512   /* sinkhorn threads; 2 rows each */

/* ---------------- scratch (device globals: no runtime allocation) ------- */
__device__ float g_xn[BB*NN*DD];
__device__ float g_ksq[BB*NN];
__device__ float g_wilogit[BB*NN];
__device__ float g_slots[BB*SS*DD];
__device__ float g_qk[BB*SS*DD];   /* Wk @ q, per slot */
__device__ float g_qsq[BB*SS];
__device__ float g_logb[BB*SS];
__device__ float g_praw[BB*SS*DD]; /* attn @ xn */

/* ---------------- helpers ---------------- */
__device__ __forceinline__ float warpSum(float v){
#pragma unroll
  for (int o=16;o>0;o>>=1) v += __shfl_down_sync(0xffffffffu, v, o);
  return v;
}
__device__ __forceinline__ float warpMax(float v){
#pragma unroll
  for (int o=16;o>0;o>>=1) v = fmaxf(v, __shfl_down_sync(0xffffffffu, v, o));
  return v;
}
__device__ __forceinline__ void warpSum4(float&a,float&b,float&c,float&d){
#pragma unroll
  for (int o=16;o>0;o>>=1){
    a += __shfl_down_sync(0xffffffffu, a, o);
    b += __shfl_down_sync(0xffffffffu, b, o);
    c += __shfl_down_sync(0xffffffffu, c, o);
    d += __shfl_down_sync(0xffffffffu, d, o);
  }
}

/* ------------- slotsnorm (+ first-iter slots init): sn=LN(slots), q,
                 qk=Wk@q, qsq, log_b ------------------------------------- */
__global__ void slotsnorm_kernel(const float* __restrict__ Wq,
   const float* __restrict__ Wk,
   const float* __restrict__ lng, const float* __restrict__ lnb,
   const float* __restrict__ ws_w, const float* __restrict__ ws_b,
   const float* __restrict__ sinit, const float* __restrict__ mu,
   const float* __restrict__ lsig, int first)
{
  int b = blockIdx.x;
  int sI = threadIdx.y;  /* 0..10 */
  int d  = threadIdx.x;  /* 0..63 */
  int lane = d&31, half = d>>5;
  __shared__ float sn[11][64];
  __shared__ float qsh[11][64];
  __shared__ float part[11][2];
  __shared__ float lg[11];
  int row = b*SS + sI;

  float x;
  if (first){
    x = mu[d] + expf(lsig[d]) * sinit[row*DD + d];
    g_slots[row*DD + d] = x;
  } else {
    x = g_slots[row*DD + d];
  }
  float s = warpSum(x);
  if (lane==0) part[sI][half]=s;
  __syncthreads();
  float mean = (part[sI][0]+part[sI][1])*(1.f/64.f);
  float c = x-mean;
  __syncthreads();
  s = warpSum(c*c);
  if (lane==0) part[sI][half]=s;
  __syncthreads();
  float var=(part[sI][0]+part[sI][1])*(1.f/64.f);
  float v = c*rsqrtf(var+1e-5f)*lng[d]+lnb[d];
  sn[sI][d]=v;
  __syncthreads();

  s = warpSum(v*ws_w[d]);
  if (lane==0) part[sI][half]=s;
  __syncthreads();
  if (d==0) lg[sI] = part[sI][0]+part[sI][1] + ws_b[0];

  float qa=0.f;
#pragma unroll 16
  for (int e=0;e<64;e++) qa = fmaf(sn[sI][e], Wq[e*64+d], qa);
  qsh[sI][d]=qa;
  __syncthreads();
  s = warpSum(qa*qa);
  if (lane==0) part[sI][half]=s;
  __syncthreads();
  if (d==0) g_qsq[row]=part[sI][0]+part[sI][1];

  /* qk[sI][e=d] = sum_dd Wk[d][dd] * q[sI][dd]  (Wk row contiguous) */
  {
    const float4* wk4 = (const float4*)(Wk + d*64);
    const float4* q4  = (const float4*)(qsh[sI]);
    float acc=0.f;
#pragma unroll
    for (int e4=0;e4<16;e4++){
      float4 w = wk4[e4], q = q4[e4];
      acc += w.x*q.x + w.y*q.y + w.z*q.z + w.w*q.w;
    }
    g_qk[row*DD + d] = acc;
  }

  if (sI==0 && d==0){
    float M=lg[0];
#pragma unroll
    for (int j=1;j<11;j++) M=fmaxf(M,lg[j]);
    float ss=0.f;
#pragma unroll
    for (int j=0;j<11;j++) ss+=expf(lg[j]-M);
    float lse=M+logf(ss);
#pragma unroll
    for (int j=0;j<11;j++) g_logb[b*SS+j]=lg[j]-lse+2.3978952727983707f;
  }
}

/* ------------- preprocess: LN(inputs)->xn, ksq=|xn@Wk|^2, wi logits ----- */
__global__ void preprocess_kernel(const float* __restrict__ inp,
    const float* __restrict__ Wk,
    const float* __restrict__ lng, const float* __restrict__ lnb,
    const float* __restrict__ wi_w, const float* __restrict__ wi_b)
{
  int ty = threadIdx.y;                 /* 0..3 */
  int d  = threadIdx.x;                 /* 0..63 */
  int lane = d & 31, half = d >> 5;
  int r0 = blockIdx.x*16 + ty*4;
  __shared__ float xs[16][64];
  __shared__ float part[16][2];

  float x0 = inp[(size_t)(r0+0)*DD + d];
  float x1 = inp[(size_t)(r0+1)*DD + d];
  float x2 = inp[(size_t)(r0+2)*DD + d];
  float x3 = inp[(size_t)(r0+3)*DD + d];

  float s0=x0,s1=x1,s2=x2,s3=x3;
  warpSum4(s0,s1,s2,s3);
  if (lane==0){ part[ty*4+0][half]=s0; part[ty*4+1][half]=s1;
                part[ty*4+2][half]=s2; part[ty*4+3][half]=s3; }
  __syncthreads();
  float c0 = x0 - (part[ty*4+0][0]+part[ty*4+0][1])*(1.f/64.f);
  float c1 = x1 - (part[ty*4+1][0]+part[ty*4+1][1])*(1.f/64.f);
  float c2 = x2 - (part[ty*4+2][0]+part[ty*4+2][1])*(1.f/64.f);
  float c3 = x3 - (part[ty*4+3][0]+part[ty*4+3][1])*(1.f/64.f);
  __syncthreads();
  s0=c0*c0; s1=c1*c1; s2=c2*c2; s3=c3*c3;
  warpSum4(s0,s1,s2,s3);
  if (lane==0){ part[ty*4+0][half]=s0; part[ty*4+1][half]=s1;
                part[ty*4+2][half]=s2; part[ty*4+3][half]=s3; }
  __syncthreads();
  float gd = lng[d], bd = lnb[d];
  float xn0 = c0*rsqrtf((part[ty*4+0][0]+part[ty*4+0][1])*(1.f/64.f)+1e-5f)*gd+bd;
  float xn1 = c1*rsqrtf((part[ty*4+1][0]+part[ty*4+1][1])*(1.f/64.f)+1e-5f)*gd+bd;
  float xn2 = c2*rsqrtf((part[ty*4+2][0]+part[ty*4+2][1])*(1.f/64.f)+1e-5f)*gd+bd;
  float xn3 = c3*rsqrtf((part[ty*4+3][0]+part[ty*4+3][1])*(1.f/64.f)+1e-5f)*gd+bd;
  xs[ty*4+0][d]=xn0; xs[ty*4+1][d]=xn1; xs[ty*4+2][d]=xn2; xs[ty*4+3][d]=xn3;
  g_xn[(size_t)(r0+0)*DD+d]=xn0;
  g_xn[(size_t)(r0+1)*DD+d]=xn1;
  g_xn[(size_t)(r0+2)*DD+d]=xn2;
  g_xn[(size_t)(r0+3)*DD+d]=xn3;
  __syncthreads();

  /* k rows (internal only, for ksq) */
  float ka0=0.f,ka1=0.f,ka2=0.f,ka3=0.f;
#pragma unroll 8
  for (int e=0;e<64;e++){
    float wk = Wk[e*64+d];
    ka0 = fmaf(xs[ty*4+0][e],wk,ka0);
    ka1 = fmaf(xs[ty*4+1][e],wk,ka1);
    ka2 = fmaf(xs[ty*4+2][e],wk,ka2);
    ka3 = fmaf(xs[ty*4+3][e],wk,ka3);
  }
  __syncthreads();
  s0=ka0*ka0; s1=ka1*ka1; s2=ka2*ka2; s3=ka3*ka3;
  warpSum4(s0,s1,s2,s3);
  if (lane==0){ part[ty*4+0][half]=s0; part[ty*4+1][half]=s1;
                part[ty*4+2][half]=s2; part[ty*4+3][half]=s3; }
  __syncthreads();
  if (d<4) g_ksq[r0 + d] = part[ty*4+d][0]+part[ty*4+d][1];
  __syncthreads();
  float wd = wi_w[d];
  s0=xn0*wd; s1=xn1*wd; s2=xn2*wd; s3=xn3*wd;
  warpSum4(s0,s1,s2,s3);
  if (lane==0){ part[ty*4+0][half]=s0; part[ty*4+1][half]=s1;
                part[ty*4+2][half]=s2; part[ty*4+3][half]=s3; }
  __syncthreads();
  if (d<4) g_wilogit[r0 + d] = part[ty*4+d][0]+part[ty*4+d][1] + wi_b[0];
}

/* ------------- sinkhorn: 512 thr, 2 rows/thr, 2 CTAs/SM ----------------- */
template<class F>
__device__ __forceinline__ void colSumApply(const float* vals, float (*xp)[HT],
                                            int i, int warp, int lane, F f)
{
#pragma unroll
  for (int j=0;j<SS;j++) xp[j][i] = vals[j];
  __syncthreads();
  if (warp < SS){
    const float4* row = (const float4*)xp[warp];
    float s = 0.f;
#pragma unroll
    for (int q4=0;q4<4;q4++){
      float4 a = row[lane + q4*32];
      s += (a.x+a.y)+(a.z+a.w);
    }
    s = warpSum(s);
    if (lane==0) f(warp, s);
  }
  __syncthreads();
}

__global__ void __launch_bounds__(HT, 2) sinkhorn_kernel(float* __restrict__ attn)
{
  int b = blockIdx.x;
  int i = threadIdx.x;               /* rows i and i+512 */
  int lane = i&31, warp = i>>5;

  __shared__ float xpose[SS][HT];          /* aliases qT at start */
  __shared__ float euh_s[SHI][2][HT];
  __shared__ float evh[SHI+1][SS];
  __shared__ float dv_sh[SS];
  __shared__ float eb_sh[SS];
  __shared__ float binv_sh[SS];
  __shared__ float evcur[SS];
  __shared__ float qsq_sh[SS];
  __shared__ float red[16];
  __shared__ float bcast;

  float* qT = &xpose[0][0];                /* [64][12] = 768 floats */
  for (int idx=i; idx<SS*DD; idx+=HT){
    int sj=idx>>6, e=idx&63;
    qT[e*12+sj] = g_qk[((size_t)b*SS+sj)*DD + e];
  }
  if (i < SS){
    float lb = g_logb[b*SS+i];
    eb_sh[i]   = __expf(lb);
    binv_sh[i] = __expf(-lb);
    evcur[i]   = 1.f;
    qsq_sh[i]  = g_qsq[b*SS+i];
  }
  __syncthreads();

  /* K = exp(-dist), two rows; dot = xn . (Wk q) */
  float K0[SS], K1[SS];
  {
    float d0[SS], d1[SS];
#pragma unroll
    for (int j=0;j<SS;j++){ d0[j]=0.f; d1[j]=0.f; }
    const float4* kr0 = (const float4*)(g_xn + ((size_t)b*NN + i)*DD);
    const float4* kr1 = (const float4*)(g_xn + ((size_t)b*NN + i + HT)*DD);
#pragma unroll
    for (int e4=0;e4<16;e4++){
      float4 a = kr0[e4];
      float4 c = kr1[e4];
      int e = e4*4;
#pragma unroll
      for (int j=0;j<SS;j++){
        d0[j]=fmaf(a.x, qT[(e+0)*12+j], d0[j]);
        d0[j]=fmaf(a.y, qT[(e+1)*12+j], d0[j]);
        d0[j]=fmaf(a.z, qT[(e+2)*12+j], d0[j]);
        d0[j]=fmaf(a.w, qT[(e+3)*12+j], d0[j]);
        d1[j]=fmaf(c.x, qT[(e+0)*12+j], d1[j]);
        d1[j]=fmaf(c.y, qT[(e+1)*12+j], d1[j]);
        d1[j]=fmaf(c.z, qT[(e+2)*12+j], d1[j]);
        d1[j]=fmaf(c.w, qT[(e+3)*12+j], d1[j]);
      }
    }
    float ks0 = g_ksq[b*NN+i];
    float ks1 = g_ksq[b*NN+i+HT];
#pragma unroll
    for (int j=0;j<SS;j++){
      float q2 = qsq_sh[j];
      K0[j] = __expf(-sqrtf(fmaxf(ks0 + q2 - 2.f*d0[j], 1e-12f)));
      K1[j] = __expf(-sqrtf(fmaxf(ks1 + q2 - 2.f*d1[j], 1e-12f)));
    }
  }

  /* a = 11*softmax(wilogit), fused */
  float a0, a1, ainv0, ainv1;
  {
    float l0 = g_wilogit[b*NN+i];
    float l1 = g_wilogit[b*NN+i+HT];
    float m = warpMax(fmaxf(l0,l1));
    if (lane==0) red[warp]=m;
    __syncthreads();
    if (warp==0){ float x = (lane<16)? red[lane] : -1e30f; x=warpMax(x); if(lane==0) bcast=x; }
    __syncthreads();
    float M = bcast;
    __syncthreads();
    float e0 = __expf(l0-M), e1 = __expf(l1-M);
    float sv = warpSum(e0+e1);
    if (lane==0) red[warp]=sv;
    __syncthreads();
    if (warp==0){ float x = (lane<16)? red[lane] : 0.f; x=warpSum(x); if(lane==0) bcast=x; }
    __syncthreads();
    float S = bcast;
    a0 = __fdividef(11.f*e0, S);  ainv0 = __fdividef(S, 11.f*e0);
    a1 = __fdividef(11.f*e1, S);  ainv1 = __fdividef(S, 11.f*e1);
    __syncthreads();
  }

  for (int mi=0; mi<MESHI; mi++){
    if (i<SS) evh[0][i]=evcur[i];
    __syncthreads();

#pragma unroll
    for (int t=1;t<=SHI;t++){
      float s0=0.f, s1=0.f;
#pragma unroll
      for (int j=0;j<SS;j++){
        float ev = evcur[j];
        s0 = fmaf(K0[j], ev, s0);
        s1 = fmaf(K1[j], ev, s1);
      }
      float eu0 = __fdividef(a0, s0);
      float eu1 = __fdividef(a1, s1);
      euh_s[t-1][0][i]=eu0;
      euh_s[t-1][1][i]=eu1;
      float cv[SS];
#pragma unroll
      for (int j=0;j<SS;j++) cv[j] = K0[j]*eu0 + K1[j]*eu1;
      colSumApply(cv, xpose, i, warp, lane, [&](int j, float sv){
        float nv = __fdividef(eb_sh[j], sv);
        evcur[j]=nv; evh[t][j]=nv;
      });
    }

    float dp0[SS], dp1[SS];
    float du50=0.f, du51=0.f;
    {
      float dvv[SS];
      float eu50 = euh_s[SHI-1][0][i];
      float eu51 = euh_s[SHI-1][1][i];
#pragma unroll
      for (int j=0;j<SS;j++){
        float ev5 = evcur[j];
        float T0 = K0[j]*eu50*ev5;
        float T1 = K1[j]*eu51*ev5;
        float Tp0 = T0 + 1e-8f, Tp1 = T1 + 1e-8f;
        float dz0 = -(__logf(Tp0) + __fdividef(T0,Tp0))*T0;
        float dz1 = -(__logf(Tp1) + __fdividef(T1,Tp1))*T1;
        dp0[j]=dz0; dp1[j]=dz1;
        du50+=dz0; du51+=dz1;
        dvv[j]=dz0+dz1;
      }
      colSumApply(dvv, xpose, i, warp, lane, [&](int j, float s){ dv_sh[j]=s; });
    }
#pragma unroll
    for (int t=SHI; t>=1; t--){
      float eut0 = euh_s[t-1][0][i];
      float eut1 = euh_s[t-1][1][i];
      float dl0 = (t==SHI) ? du50 : 0.f;
      float dl1 = (t==SHI) ? du51 : 0.f;
#pragma unroll
      for (int j=0;j<SS;j++){
        float wj = evh[t][j]*binv_sh[j];
        float c0 = dv_sh[j]*K0[j]*eut0*wj;
        float c1 = dv_sh[j]*K1[j]*eut1*wj;
        dp0[j] -= c0; dl0 -= c0;
        dp1[j] -= c1; dl1 -= c1;
      }
      float contrib[SS];
      float g0 = dl0*ainv0, g1 = dl1*ainv1;
#pragma unroll
      for (int j=0;j<SS;j++){
        float e2c = evh[t-1][j];
        float mm0 = K0[j]*eut0*e2c*g0;
        float mm1 = K1[j]*eut1*e2c*g1;
        dp0[j] -= mm0;
        dp1[j] -= mm1;
        contrib[j] = -(mm0+mm1);
      }
      if (t>1) colSumApply(contrib, xpose, i, warp, lane, [&](int j, float s){ dv_sh[j]=s; });
    }
#pragma unroll
    for (int j=0;j<SS;j++){
      K0[j] *= __expf(-dp0[j]);
      K1[j] *= __expf(-dp1[j]);
    }
    __syncthreads();
  }

  float eu0=1.f, eu1=1.f;
#pragma unroll
  for (int t=0;t<SHI;t++){
    float s0=0.f, s1=0.f;
#pragma unroll
    for (int j=0;j<SS;j++){
      float ev = evcur[j];
      s0 = fmaf(K0[j], ev, s0);
      s1 = fmaf(K1[j], ev, s1);
    }
    eu0 = __fdividef(a0, s0);
    eu1 = __fdividef(a1, s1);
    float cv[SS];
#pragma unroll
    for (int j=0;j<SS;j++) cv[j] = K0[j]*eu0 + K1[j]*eu1;
    colSumApply(cv, xpose, i, warp, lane, [&](int j, float sv){
      evcur[j] = __fdividef(eb_sh[j], sv);
    });
  }
#pragma unroll
  for (int j=0;j<SS;j++){
    float ev = evcur[j];
    attn[((size_t)b*SS+j)*NN + i]      = K0[j]*eu0*ev;
    attn[((size_t)b*SS+j)*NN + i + HT] = K1[j]*eu1*ev;
  }
}

/* ------------- praw = attn @ xn  (512 thr: thread = (group g, dim d)) --- */
/* xn read ONCE per value straight from global (coalesced); attn staged in  */
/* smem and read as broadcast float4. 3 barriers total.                     */
__global__ void __launch_bounds__(512, 2) praw_kernel(const float* __restrict__ attn)
{
  __shared__ float at[SS][NN];      /* 45KB; aliased by partials later */
  int b = blockIdx.x;
  int t = threadIdx.x;
  int g = t >> 6;                   /* 0..7  : row group (128 rows)    */
  int d = t & 63;                   /* 0..63 : output dim              */

  /* stage attn (11*1024 floats = 2816 float4) */
  {
    const float4* src = (const float4*)(attn + (size_t)b*SS*NN);
    float4* dst = (float4*)&at[0][0];
    for (int idx=t; idx<(SS*NN)/4; idx+=512) dst[idx] = src[idx];
  }
  __syncthreads();

  float acc[SS];
#pragma unroll
  for (int s=0;s<SS;s++) acc[s]=0.f;

  const float* xb = g_xn + (size_t)b*NN*DD + (size_t)(g*128)*DD + d;
#pragma unroll 4
  for (int k=0;k<32;k++){
    int r4 = k*4;
    float x0 = xb[(size_t)(r4+0)*DD];
    float x1 = xb[(size_t)(r4+1)*DD];
    float x2 = xb[(size_t)(r4+2)*DD];
    float x3 = xb[(size_t)(r4+3)*DD];
    int base = g*128 + r4;
#pragma unroll
    for (int s=0;s<SS;s++){
      float4 a4 = *(const float4*)&at[s][base];
      acc[s] = fmaf(a4.x, x0, fmaf(a4.y, x1, fmaf(a4.z, x2, fmaf(a4.w, x3, acc[s]))));
    }
  }
  __syncthreads();                 /* all at reads done */

  float* partial = &at[0][0];      /* alias: [g][s][d] = 8*11*64 floats */
#pragma unroll
  for (int s=0;s<SS;s++) partial[(g*SS+s)*64 + d] = acc[s];
  __syncthreads();

  for (int idx=t; idx<SS*DD; idx+=512){
    int s = idx>>6, dd = idx&63;
    float sum=0.f;
#pragma unroll
    for (int gg=0; gg<8; gg++) sum += partial[(gg*SS+s)*64 + dd];
    g_praw[((size_t)b*SS+s)*DD + dd] = sum;
  }
}

/* ------------- GRU: updates = praw@Wv, GRU cell, LN, MLP ---------------- */
__global__ void __launch_bounds__(704, 2) gru_kernel(
  const float* __restrict__ Wv,
  const float* __restrict__ Wih, const float* __restrict__ Whh,
  const float* __restrict__ bih, const float* __restrict__ bhh,
  const float* __restrict__ fc1w, const float* __restrict__ fc1b,
  const float* __restrict__ fc2w, const float* __restrict__ fc2b,
  const float* __restrict__ lng, const float* __restrict__ lnb,
  float* __restrict__ out_slots)
{
  int b = blockIdx.x;
  int t = threadIdx.x;        /* 0..703 */
  int sI = t>>6, d = t&63;
  int lane = d&31, half = d>>5;
  __shared__ float praw_sh[11][64];
  __shared__ float xsh[11][64], hsh[11][64], ysh[11][64];
  __shared__ float hid[11][128];
  __shared__ float part[11][2];

  int row = b*SS + sI;
  praw_sh[sI][d] = g_praw[(size_t)row*DD + d];
  float h = g_slots[row*DD+d];
  hsh[sI][d] = h;
  __syncthreads();

  /* updates = praw @ Wv */
  float upd = 0.f;
#pragma unroll 8
  for (int e=0;e<64;e++) upd = fmaf(praw_sh[sI][e], Wv[e*64+d], upd);
  xsh[sI][d] = upd;
  __syncthreads();

  float gi_r=bih[d], gi_z=bih[64+d], gi_n=bih[128+d];
  float gh_r=bhh[d], gh_z=bhh[64+d], gh_n=bhh[128+d];
#pragma unroll 8
  for (int e=0;e<64;e++){
    float xe=xsh[sI][e], he=hsh[sI][e];
    gi_r=fmaf(xe, Wih[e*192+d],     gi_r);
    gi_z=fmaf(xe, Wih[e*192+64+d],  gi_z);
    gi_n=fmaf(xe, Wih[e*192+128+d], gi_n);
    gh_r=fmaf(he, Whh[e*192+d],     gh_r);
    gh_z=fmaf(he, Whh[e*192+64+d],  gh_z);
    gh_n=fmaf(he, Whh[e*192+128+d], gh_n);
  }
  float r  = 1.f/(1.f+__expf(-(gi_r+gh_r)));
  float z  = 1.f/(1.f+__expf(-(gi_z+gh_z)));
  float ex = __expf(-2.f*(gi_n + r*gh_n));
  float nn = (1.f-ex)/(1.f+ex);
  float hnew = (1.f-z)*nn + z*h;

  float s = warpSum(hnew);
  if (lane==0) part[sI][half]=s;
  __syncthreads();
  float mean=(part[sI][0]+part[sI][1])*(1.f/64.f);
  float c = hnew-mean;
  __syncthreads();
  s = warpSum(c*c);
  if (lane==0) part[sI][half]=s;
  __syncthreads();
  float var=(part[sI][0]+part[sI][1])*(1.f/64.f);
  float y = c*rsqrtf(var+1e-5f)*lng[d]+lnb[d];
  ysh[sI][d]=y;
  __syncthreads();

  float h0=fc1b[d], h1=fc1b[64+d];
#pragma unroll 8
  for (int e=0;e<64;e++){
    float ye=ysh[sI][e];
    h0=fmaf(ye, fc1w[e*128+d],    h0);
    h1=fmaf(ye, fc1w[e*128+64+d], h1);
  }
  hid[sI][d]=fmaxf(h0,0.f); hid[sI][64+d]=fmaxf(h1,0.f);
  __syncthreads();

  float o=fc2b[d];
#pragma unroll 16
  for (int hh=0; hh<128; hh++) o=fmaf(hid[sI][hh], fc2w[hh*64+d], o);
  float outv = hnew + o;
  g_slots[row*DD+d]=outv;
  out_slots[row*DD+d]=outv;
}

/* ------------------------------- launcher ------------------------------- */
extern "C" void kernel_launch(void* const* d_in, const int* in_sizes, int n_in,
                              void* d_out, int out_size)
{
  const float* inputs          = (const float*)d_in[0];
  const float* slots_init      = (const float*)d_in[1];
  const float* slots_mu        = (const float*)d_in[2];
  const float* slots_log_sigma = (const float*)d_in[3];
  const float* Wq      = (const float*)d_in[4];
  const float* Wk      = (const float*)d_in[5];
  const float* Wv      = (const float*)d_in[6];
  const float* gru_Wih = (const float*)d_in[7];
  const float* gru_Whh = (const float*)d_in[8];
  const float* gru_bih = (const float*)d_in[9];
  const float* gru_bhh = (const float*)d_in[10];
  const float* fc1_w   = (const float*)d_in[11];
  const float* fc1_b   = (const float*)d_in[12];
  const float* fc2_w   = (const float*)d_in[13];
  const float* fc2_b   = (const float*)d_in[14];
  const float* ln_in_g = (const float*)d_in[15];
  const float* ln_in_b = (const float*)d_in[16];
  const float* ln_sl_g = (const float*)d_in[17];
  const float* ln_sl_b = (const float*)d_in[18];
  const float* ln_ff_g = (const float*)d_in[19];
  const float* ln_ff_b = (const float*)d_in[20];
  const float* wi_w    = (const float*)d_in[21];
  const float* wi_b    = (const float*)d_in[22];
  const float* ws_w    = (const float*)d_in[23];
  const float* ws_b    = (const float*)d_in[24];

  float* out       = (float*)d_out;
  float* out_slots = out;                      /* (B,S,D)  */
  float* out_attn  = out + BB*SS*DD;           /* (B,S,N)  */

  /* launch #4 = praw_kernel (profiled slot) */
  slotsnorm_kernel<<<BB, dim3(64,11)>>>(Wq, Wk, ln_sl_g, ln_sl_b, ws_w, ws_b,
                                        slots_init, slots_mu, slots_log_sigma, 1);
  preprocess_kernel<<<BB*NN/16, dim3(64,4)>>>(inputs, Wk, ln_in_g, ln_in_b, wi_w, wi_b);

  for (int it=0; it<NITERS; it++){
    if (it > 0)
      slotsnorm_kernel<<<BB, dim3(64,11)>>>(Wq, Wk, ln_sl_g, ln_sl_b, ws_w, ws_b,
                                            slots_init, slots_mu, slots_log_sigma, 0);
    sinkhorn_kernel<<<BB, HT>>>(out_attn);
    praw_kernel<<<BB, 512>>>(out_attn);
    gru_kernel<<<BB, 704>>>(Wv, gru_Wih, gru_Whh, gru_bih, gru_bhh,
                            fc1_w, fc1_b, fc2_w, fc2_b,
                            ln_ff_g, ln_ff_b, out_slots);
  }
  (void)in_sizes; (void)n_in; (void)out_size;
}